// round 2
// baseline (speedup 1.0000x reference)
#include <cuda_runtime.h>
#include <cstdint>

#define N_NODES 100000
#define FDIM 64                 // IN_W == OUT_W == 64
#define SELF_LOOP_W 2.0f

// ---- scratch (no cudaMalloc allowed) ----
__device__ float g_deg [N_NODES];
__device__ float g_dinv[N_NODES];
__device__ float g_h   [(size_t)N_NODES * FDIM];

// ---------------------------------------------------------------------------
// K1: deg[i] = self-loop weight
__global__ void k_deg_init() {
    int i = blockIdx.x * blockDim.x + threadIdx.x;
    if (i < N_NODES) g_deg[i] = SELF_LOOP_W;
}

// K2: deg[dst] += w[e]      (edge_index is int32: JAX canonicalizes int64->int32)
__global__ void k_deg_acc(const int* __restrict__ ei,
                          const float* __restrict__ w, int E) {
    int e = blockIdx.x * blockDim.x + threadIdx.x;
    if (e < E) {
        int d = ei[E + e];      // dst row of edge_index [2, E]
        atomicAdd(&g_deg[d], w[e]);
    }
}

// K3: dinv = rsqrt(deg)   (deg >= 2 always, self-loop guarantees > 0)
__global__ void k_dinv() {
    int i = blockIdx.x * blockDim.x + threadIdx.x;
    if (i < N_NODES) g_dinv[i] = rsqrtf(g_deg[i]);
}

// ---------------------------------------------------------------------------
// K4: h = x @ W ; out = h * (2*dinv^2) + b   (also initializes poisoned d_out)
// 256 threads/block: 32 rows per block, 8 threads per row, 8 cols per thread.
__global__ void k_gemm_self(const float* __restrict__ x,
                            const float* __restrict__ W,
                            const float* __restrict__ b,
                            float* __restrict__ out) {
    __shared__ float Ws[FDIM * FDIM];     // 16 KB
    __shared__ float xs[32 * FDIM];       // 8 KB

    int tid = threadIdx.x;

    // load W (64x64) via float4
    {
        const float4* W4  = (const float4*)W;
        float4*       Ws4 = (float4*)Ws;
        #pragma unroll
        for (int i = tid; i < FDIM * FDIM / 4; i += 256) Ws4[i] = W4[i];
    }

    int row0  = blockIdx.x * 32;
    int nrows = min(32, N_NODES - row0);

    // load 32 rows of x via float4
    {
        const float4* x4  = (const float4*)(x + (size_t)row0 * FDIM);
        float4*       xs4 = (float4*)xs;
        for (int i = tid; i < nrows * (FDIM / 4); i += 256) xs4[i] = x4[i];
    }
    __syncthreads();

    int r = tid >> 3;             // 0..31 local row
    int c = (tid & 7) * 8;        // 0,8,...,56
    if (r < nrows) {
        float acc[8];
        #pragma unroll
        for (int j = 0; j < 8; j++) acc[j] = 0.f;

        #pragma unroll
        for (int k = 0; k < FDIM; k++) {
            float xv = xs[r * FDIM + k];
            const float4* wrow = (const float4*)(&Ws[k * FDIM + c]);
            float4 w0 = wrow[0], w1 = wrow[1];
            acc[0] += xv * w0.x; acc[1] += xv * w0.y;
            acc[2] += xv * w0.z; acc[3] += xv * w0.w;
            acc[4] += xv * w1.x; acc[5] += xv * w1.y;
            acc[6] += xv * w1.z; acc[7] += xv * w1.w;
        }

        int row = row0 + r;
        float di = g_dinv[row];
        float sc = 2.0f * di * di;          // self-loop: dinv * 2.0 * dinv
        size_t base = (size_t)row * FDIM + c;
        #pragma unroll
        for (int j = 0; j < 8; j++) {
            g_h[base + j] = acc[j];
            out[base + j] = acc[j] * sc + b[c + j];
        }
    }
}

// ---------------------------------------------------------------------------
// K5: edge scatter. 16 lanes per edge, float4 per lane (256B row).
__global__ void k_scatter(const int* __restrict__ ei,
                          const float* __restrict__ w,
                          float* __restrict__ out, int E) {
    int t = blockIdx.x * blockDim.x + threadIdx.x;
    int g = t >> 4;
    int l = t & 15;
    if (g >= E) return;

    int s = __ldg(&ei[g]);
    int d = __ldg(&ei[E + g]);
    float coef = g_dinv[s] * w[g] * g_dinv[d];

    const float4* hv = (const float4*)(g_h + (size_t)s * FDIM);
    float4 v = hv[l];

    float4* op = (float4*)(out + (size_t)d * FDIM) + l;
    asm volatile("red.global.add.v4.f32 [%0], {%1, %2, %3, %4};"
                 :: "l"(op),
                    "f"(v.x * coef), "f"(v.y * coef),
                    "f"(v.z * coef), "f"(v.w * coef)
                 : "memory");
}

// ---------------------------------------------------------------------------
extern "C" void kernel_launch(void* const* d_in, const int* in_sizes, int n_in,
                              void* d_out, int out_size) {
    const float* x   = (const float*)d_in[0];       // [N, 64]
    const float* ew  = (const float*)d_in[1];       // [E]
    const float* W   = (const float*)d_in[2];       // [64, 64]
    const float* b   = (const float*)d_in[3];       // [64]
    const int*   ei  = (const int*)d_in[4];         // [2, E] int32 (JAX x64 off)
    // d_in[5] = batch, unused

    int E = in_sizes[1];
    float* out = (float*)d_out;

    k_deg_init<<<(N_NODES + 255) / 256, 256>>>();
    k_deg_acc <<<(E + 255) / 256, 256>>>(ei, ew, E);
    k_dinv    <<<(N_NODES + 255) / 256, 256>>>();
    k_gemm_self<<<(N_NODES + 31) / 32, 256>>>(x, W, b, out);

    long long st = (long long)E * 16;
    k_scatter<<<(unsigned)((st + 255) / 256), 256>>>(ei, ew, out, E);
}

// round 5
// speedup vs baseline: 1.5661x; 1.5661x over previous
#include <cuda_runtime.h>
#include <cstdint>

#define N_NODES 100000
#define FDIM 64                 // IN_W == OUT_W == 64
#define SELF_LOOP_W 2.0f

// ---- scratch (no cudaMalloc allowed) ----
__device__ float g_deg [N_NODES];
__device__ float g_dinv[N_NODES];
__device__ float g_h   [(size_t)N_NODES * FDIM];

// ---------------------------------------------------------------------------
// K1: deg[i] = self-loop weight
__global__ void k_deg_init() {
    int i = blockIdx.x * blockDim.x + threadIdx.x;
    if (i < N_NODES) g_deg[i] = SELF_LOOP_W;
}

// K2: deg[dst] += w[e]   (edge_index is int32: JAX canonicalizes int64->int32)
__global__ void k_deg_acc(const int* __restrict__ ei,
                          const float* __restrict__ w, int E) {
    int e = blockIdx.x * blockDim.x + threadIdx.x;
    if (e < E) {
        int d = ei[E + e];
        atomicAdd(&g_deg[d], w[e]);
    }
}

// K3: dinv = rsqrt(deg)
__global__ void k_dinv() {
    int i = blockIdx.x * blockDim.x + threadIdx.x;
    if (i < N_NODES) g_dinv[i] = rsqrtf(g_deg[i]);
}

// ---------------------------------------------------------------------------
// K4: register-blocked SGEMM fused with self-loop epilogue.
//   h = x @ W ;  out = h * (2*dinv^2) + b
// Block tile: 96 rows x 64 cols, 96 threads, 8x8 per thread.
//   ty = tid>>3 (0..11)  -> rows ty*8 .. ty*8+7
//   tx = tid&7  (0..7)   -> cols tx*8 .. tx*8+7
// smem budget: Ws 16384 B + xs 96*68*4 = 26112 B -> 42496 B < 48 KB limit.
// x-tile stored with XOR-4 swizzle on the k column per 8-row group so the
// 4 distinct A addresses per warp hit 4 distinct banks (8-lane broadcast each).
#define BM 96
#define NTHREADS 96
#define XS_STRIDE 68            // floats; 68*4=272B, 16B aligned

__global__ __launch_bounds__(NTHREADS)
void k_gemm_self(const float* __restrict__ x,
                 const float* __restrict__ W,
                 const float* __restrict__ bias,
                 float* __restrict__ out) {
    __shared__ float Ws[FDIM * FDIM];        // 16 KB
    __shared__ float xs[BM * XS_STRIDE];     // 25.5 KB

    int tid  = threadIdx.x;
    int row0 = blockIdx.x * BM;
    int nrows = min(BM, N_NODES - row0);

    // ---- load W (1024 float4) ----
    {
        const float4* W4  = (const float4*)W;
        float4*       Ws4 = (float4*)Ws;
        for (int i = tid; i < FDIM * FDIM / 4; i += NTHREADS) Ws4[i] = W4[i];
    }

    // ---- load x tile (96 rows x 16 float4 = 1536 float4, 16/thread) ----
    {
        const float4* x4 = (const float4*)(x + (size_t)row0 * FDIM);
        #pragma unroll
        for (int i = 0; i < 16; i++) {
            int idx = tid + i * NTHREADS;      // 0..1535
            int row = idx >> 4;                // 0..95
            int kq  = idx & 15;                // float4 col 0..15
            float4 v = (row < nrows) ? x4[row * 16 + kq]
                                     : make_float4(0.f, 0.f, 0.f, 0.f);
            int kq_s = kq ^ ((row >> 3) & 3);  // XOR swizzle (float4 units)
            *(float4*)&xs[row * XS_STRIDE + kq_s * 4] = v;
        }
    }
    __syncthreads();

    int ty = tid >> 3;       // 0..11
    int tx = tid & 7;        // 0..7
    int swz = (ty & 3) << 2; // k-column XOR for this row group (float units)

    float acc[8][8];
    #pragma unroll
    for (int i = 0; i < 8; i++)
        #pragma unroll
        for (int j = 0; j < 8; j++) acc[i][j] = 0.f;

    const float* xbase = &xs[(ty * 8) * XS_STRIDE];
    const float* wbase = &Ws[tx * 8];

    #pragma unroll 4
    for (int k = 0; k < FDIM; k++) {
        int kk = k ^ swz;
        float a[8];
        #pragma unroll
        for (int i = 0; i < 8; i++) a[i] = xbase[i * XS_STRIDE + kk];

        float4 b0 = *(const float4*)&wbase[k * FDIM];
        float4 b1 = *(const float4*)&wbase[k * FDIM + 4];
        float b[8] = {b0.x, b0.y, b0.z, b0.w, b1.x, b1.y, b1.z, b1.w};

        #pragma unroll
        for (int i = 0; i < 8; i++)
            #pragma unroll
            for (int j = 0; j < 8; j++)
                acc[i][j] += a[i] * b[j];
    }

    // ---- epilogue: h, out = h*2*dinv^2 + bias ----
    float4 bb0 = *(const float4*)&bias[tx * 8];
    float4 bb1 = *(const float4*)&bias[tx * 8 + 4];
    float bv[8] = {bb0.x, bb0.y, bb0.z, bb0.w, bb1.x, bb1.y, bb1.z, bb1.w};

    #pragma unroll
    for (int i = 0; i < 8; i++) {
        int row = row0 + ty * 8 + i;
        if (row >= N_NODES) break;
        float di = g_dinv[row];
        float sc = 2.0f * di * di;
        size_t base = (size_t)row * FDIM + tx * 8;
        float4 h0 = make_float4(acc[i][0], acc[i][1], acc[i][2], acc[i][3]);
        float4 h1 = make_float4(acc[i][4], acc[i][5], acc[i][6], acc[i][7]);
        *(float4*)&g_h[base]     = h0;
        *(float4*)&g_h[base + 4] = h1;
        float4 o0 = make_float4(h0.x * sc + bv[0], h0.y * sc + bv[1],
                                h0.z * sc + bv[2], h0.w * sc + bv[3]);
        float4 o1 = make_float4(h1.x * sc + bv[4], h1.y * sc + bv[5],
                                h1.z * sc + bv[6], h1.w * sc + bv[7]);
        *(float4*)&out[base]     = o0;
        *(float4*)&out[base + 4] = o1;
    }
}

// ---------------------------------------------------------------------------
// K5: edge scatter. 16 lanes per edge, float4 per lane (256B row).
__global__ void k_scatter(const int* __restrict__ ei,
                          const float* __restrict__ w,
                          float* __restrict__ out, int E) {
    int t = blockIdx.x * blockDim.x + threadIdx.x;
    int g = t >> 4;
    int l = t & 15;
    if (g >= E) return;

    int s = __ldg(&ei[g]);
    int d = __ldg(&ei[E + g]);
    float coef = g_dinv[s] * w[g] * g_dinv[d];

    const float4* hv = (const float4*)(g_h + (size_t)s * FDIM);
    float4 v = hv[l];

    float4* op = (float4*)(out + (size_t)d * FDIM) + l;
    asm volatile("red.global.add.v4.f32 [%0], {%1, %2, %3, %4};"
                 :: "l"(op),
                    "f"(v.x * coef), "f"(v.y * coef),
                    "f"(v.z * coef), "f"(v.w * coef)
                 : "memory");
}

// ---------------------------------------------------------------------------
extern "C" void kernel_launch(void* const* d_in, const int* in_sizes, int n_in,
                              void* d_out, int out_size) {
    const float* x   = (const float*)d_in[0];       // [N, 64]
    const float* ew  = (const float*)d_in[1];       // [E]
    const float* W   = (const float*)d_in[2];       // [64, 64]
    const float* b   = (const float*)d_in[3];       // [64]
    const int*   ei  = (const int*)d_in[4];         // [2, E] int32
    // d_in[5] = batch, unused

    int E = in_sizes[1];
    float* out = (float*)d_out;

    k_deg_init<<<(N_NODES + 255) / 256, 256>>>();
    k_deg_acc <<<(E + 255) / 256, 256>>>(ei, ew, E);
    k_dinv    <<<(N_NODES + 255) / 256, 256>>>();
    k_gemm_self<<<(N_NODES + BM - 1) / BM, NTHREADS>>>(x, W, b, out);

    long long st = (long long)E * 16;
    k_scatter<<<(unsigned)((st + 255) / 256), 256>>>(ei, ew, out, E);
}

// round 6
// speedup vs baseline: 1.6298x; 1.0407x over previous
#include <cuda_runtime.h>
#include <cstdint>

#define N_NODES 100000
#define FDIM 64                 // IN_W == OUT_W == 64
#define SELF_LOOP_W 2.0f
#define E_MAX 2000000
#define SCAN_NB ((N_NODES + 255) / 256)   // 391 blocks of 256

// ---- scratch (no cudaMalloc allowed) ----
__device__ float g_deg [N_NODES];
__device__ float g_dinv[N_NODES];
__device__ float g_h   [(size_t)N_NODES * FDIM];
__device__ int   g_cnt [N_NODES];
__device__ int   g_off [N_NODES];
__device__ int   g_cur [N_NODES];
__device__ int   g_part[512];
__device__ int   g_srcs[E_MAX];
__device__ float g_coef[E_MAX];

// ---------------------------------------------------------------------------
// K1: deg[i] = self-loop weight ; cnt[i] = 0
__global__ void k_init() {
    int i = blockIdx.x * blockDim.x + threadIdx.x;
    if (i < N_NODES) { g_deg[i] = SELF_LOOP_W; g_cnt[i] = 0; }
}

// K2: deg[dst] += w[e] ; cnt[dst]++   (edge_index int32: JAX x64 off)
__global__ void k_deg_acc(const int* __restrict__ ei,
                          const float* __restrict__ w, int E) {
    int e = blockIdx.x * blockDim.x + threadIdx.x;
    if (e < E) {
        int d = ei[E + e];
        atomicAdd(&g_deg[d], w[e]);
        atomicAdd(&g_cnt[d], 1);
    }
}

// K3: dinv = rsqrt(deg)   (deg >= 2 always)
__global__ void k_dinv() {
    int i = blockIdx.x * blockDim.x + threadIdx.x;
    if (i < N_NODES) g_dinv[i] = rsqrtf(g_deg[i]);
}

// ---------------------------------------------------------------------------
// Exclusive prefix scan of g_cnt -> g_off (3 kernels).
__global__ void k_scan1() {
    __shared__ int sm[256];
    int t = threadIdx.x;
    int i = blockIdx.x * 256 + t;
    int v = (i < N_NODES) ? g_cnt[i] : 0;
    sm[t] = v;
    __syncthreads();
    #pragma unroll
    for (int ofs = 1; ofs < 256; ofs <<= 1) {
        int a = (t >= ofs) ? sm[t - ofs] : 0;
        __syncthreads();
        sm[t] += a;
        __syncthreads();
    }
    if (i < N_NODES) g_off[i] = sm[t] - v;        // exclusive within block
    if (t == 255) g_part[blockIdx.x] = sm[255];   // block total
}

__global__ void k_scan2() {   // single block of 512 threads; SCAN_NB <= 512
    __shared__ int sm[512];
    int t = threadIdx.x;
    int v = (t < SCAN_NB) ? g_part[t] : 0;
    sm[t] = v;
    __syncthreads();
    #pragma unroll
    for (int ofs = 1; ofs < 512; ofs <<= 1) {
        int a = (t >= ofs) ? sm[t - ofs] : 0;
        __syncthreads();
        sm[t] += a;
        __syncthreads();
    }
    if (t < SCAN_NB) g_part[t] = sm[t] - v;       // exclusive block bases
}

__global__ void k_scan3() {   // add base, seed cursors
    int i = blockIdx.x * blockDim.x + threadIdx.x;
    if (i < N_NODES) {
        int o = g_off[i] + g_part[i >> 8];
        g_off[i] = o;
        g_cur[i] = o;
    }
}

// ---------------------------------------------------------------------------
// K4: bucket edges by dst: srcs[pos], coef[pos] = dinv[s]*w*dinv[d]
__global__ void k_bucket(const int* __restrict__ ei,
                         const float* __restrict__ w, int E) {
    int e = blockIdx.x * blockDim.x + threadIdx.x;
    if (e < E) {
        int s = ei[e];
        int d = ei[E + e];
        int pos = atomicAdd(&g_cur[d], 1);
        g_srcs[pos] = s;
        g_coef[pos] = g_dinv[s] * w[e] * g_dinv[d];
    }
}

// ---------------------------------------------------------------------------
// K5: register-blocked SGEMM fused with self-loop epilogue (unchanged).
#define BM 96
#define NTHREADS 96
#define XS_STRIDE 68

__global__ __launch_bounds__(NTHREADS)
void k_gemm_self(const float* __restrict__ x,
                 const float* __restrict__ W,
                 const float* __restrict__ bias,
                 float* __restrict__ out) {
    __shared__ float Ws[FDIM * FDIM];        // 16 KB
    __shared__ float xs[BM * XS_STRIDE];     // 25.5 KB

    int tid  = threadIdx.x;
    int row0 = blockIdx.x * BM;
    int nrows = min(BM, N_NODES - row0);

    {
        const float4* W4  = (const float4*)W;
        float4*       Ws4 = (float4*)Ws;
        for (int i = tid; i < FDIM * FDIM / 4; i += NTHREADS) Ws4[i] = W4[i];
    }
    {
        const float4* x4 = (const float4*)(x + (size_t)row0 * FDIM);
        #pragma unroll
        for (int i = 0; i < 16; i++) {
            int idx = tid + i * NTHREADS;
            int row = idx >> 4;
            int kq  = idx & 15;
            float4 v = (row < nrows) ? x4[row * 16 + kq]
                                     : make_float4(0.f, 0.f, 0.f, 0.f);
            int kq_s = kq ^ ((row >> 3) & 3);
            *(float4*)&xs[row * XS_STRIDE + kq_s * 4] = v;
        }
    }
    __syncthreads();

    int ty = tid >> 3;
    int tx = tid & 7;
    int swz = (ty & 3) << 2;

    float acc[8][8];
    #pragma unroll
    for (int i = 0; i < 8; i++)
        #pragma unroll
        for (int j = 0; j < 8; j++) acc[i][j] = 0.f;

    const float* xbase = &xs[(ty * 8) * XS_STRIDE];
    const float* wbase = &Ws[tx * 8];

    #pragma unroll 4
    for (int k = 0; k < FDIM; k++) {
        int kk = k ^ swz;
        float a[8];
        #pragma unroll
        for (int i = 0; i < 8; i++) a[i] = xbase[i * XS_STRIDE + kk];

        float4 b0 = *(const float4*)&wbase[k * FDIM];
        float4 b1 = *(const float4*)&wbase[k * FDIM + 4];
        float b[8] = {b0.x, b0.y, b0.z, b0.w, b1.x, b1.y, b1.z, b1.w};

        #pragma unroll
        for (int i = 0; i < 8; i++)
            #pragma unroll
            for (int j = 0; j < 8; j++)
                acc[i][j] += a[i] * b[j];
    }

    float4 bb0 = *(const float4*)&bias[tx * 8];
    float4 bb1 = *(const float4*)&bias[tx * 8 + 4];
    float bv[8] = {bb0.x, bb0.y, bb0.z, bb0.w, bb1.x, bb1.y, bb1.z, bb1.w};

    #pragma unroll
    for (int i = 0; i < 8; i++) {
        int row = row0 + ty * 8 + i;
        if (row >= N_NODES) break;
        float di = g_dinv[row];
        float sc = 2.0f * di * di;
        size_t base = (size_t)row * FDIM + tx * 8;
        float4 h0 = make_float4(acc[i][0], acc[i][1], acc[i][2], acc[i][3]);
        float4 h1 = make_float4(acc[i][4], acc[i][5], acc[i][6], acc[i][7]);
        *(float4*)&g_h[base]     = h0;
        *(float4*)&g_h[base + 4] = h1;
        float4 o0 = make_float4(h0.x * sc + bv[0], h0.y * sc + bv[1],
                                h0.z * sc + bv[2], h0.w * sc + bv[3]);
        float4 o1 = make_float4(h1.x * sc + bv[4], h1.y * sc + bv[5],
                                h1.z * sc + bv[6], h1.w * sc + bv[7]);
        *(float4*)&out[base]     = o0;
        *(float4*)&out[base + 4] = o1;
    }
}

// ---------------------------------------------------------------------------
// K6: gather-accumulate. 16 lanes per dst node; loop over its edge bucket,
// accumulate in registers, single RMW of the out row. No atomics.
__global__ void k_gather(float* __restrict__ out) {
    int t = blockIdx.x * blockDim.x + threadIdx.x;
    int node = t >> 4;
    int l    = t & 15;
    if (node >= N_NODES) return;

    int start = g_off[node];
    int n     = g_cnt[node];

    float4 acc = make_float4(0.f, 0.f, 0.f, 0.f);
    if (n > 0) {
        int   s = g_srcs[start];
        float c = g_coef[start];
        for (int j = 0; j < n; j++) {
            int   s_next = 0; float c_next = 0.f;
            if (j + 1 < n) {                      // prefetch next edge
                s_next = g_srcs[start + j + 1];
                c_next = g_coef[start + j + 1];
            }
            float4 v = ((const float4*)(g_h + (size_t)s * FDIM))[l];
            acc.x += c * v.x; acc.y += c * v.y;
            acc.z += c * v.z; acc.w += c * v.w;
            s = s_next; c = c_next;
        }
    }

    float4* op = (float4*)(out + (size_t)node * FDIM) + l;
    float4 o = *op;
    o.x += acc.x; o.y += acc.y; o.z += acc.z; o.w += acc.w;
    *op = o;
}

// ---------------------------------------------------------------------------
extern "C" void kernel_launch(void* const* d_in, const int* in_sizes, int n_in,
                              void* d_out, int out_size) {
    const float* x   = (const float*)d_in[0];       // [N, 64]
    const float* ew  = (const float*)d_in[1];       // [E]
    const float* W   = (const float*)d_in[2];       // [64, 64]
    const float* b   = (const float*)d_in[3];       // [64]
    const int*   ei  = (const int*)d_in[4];         // [2, E] int32
    // d_in[5] = batch, unused

    int E = in_sizes[1];
    float* out = (float*)d_out;

    k_init   <<<(N_NODES + 255) / 256, 256>>>();
    k_deg_acc<<<(E + 255) / 256, 256>>>(ei, ew, E);
    k_dinv   <<<(N_NODES + 255) / 256, 256>>>();

    k_scan1<<<SCAN_NB, 256>>>();
    k_scan2<<<1, 512>>>();
    k_scan3<<<(N_NODES + 255) / 256, 256>>>();

    k_bucket<<<(E + 255) / 256, 256>>>(ei, ew, E);

    k_gemm_self<<<(N_NODES + BM - 1) / BM, NTHREADS>>>(x, W, b, out);

    long long gt = (long long)N_NODES * 16;
    k_gather<<<(unsigned)((gt + 255) / 256), 256>>>(out);
}

// round 7
// speedup vs baseline: 1.8233x; 1.1187x over previous
#include <cuda_runtime.h>
#include <cstdint>

#define N_NODES 100000
#define FDIM 64                 // IN_W == OUT_W == 64
#define SELF_LOOP_W 2.0f
#define E_MAX 2000000
#define SCAN_NB ((N_NODES + 255) / 256)   // 391 blocks of 256

// ---- scratch (no cudaMalloc allowed) ----
__device__ float g_deg [N_NODES];
__device__ float g_dinv[N_NODES];
__device__ float g_h   [(size_t)N_NODES * FDIM];
__device__ int   g_cnt [N_NODES];
__device__ int   g_off [N_NODES];
__device__ int   g_cur [N_NODES];
__device__ int   g_part[512];
__device__ int2  g_pair[E_MAX];           // (src, coef-bits) interleaved

// ---------------------------------------------------------------------------
// K1: deg[i] = self-loop weight ; cnt[i] = 0
__global__ void k_init() {
    int i = blockIdx.x * blockDim.x + threadIdx.x;
    if (i < N_NODES) { g_deg[i] = SELF_LOOP_W; g_cnt[i] = 0; }
}

// K2: deg[dst] += w[e] ; cnt[dst]++
__global__ void k_deg_acc(const int* __restrict__ ei,
                          const float* __restrict__ w, int E) {
    int e = blockIdx.x * blockDim.x + threadIdx.x;
    if (e < E) {
        int d = ei[E + e];
        atomicAdd(&g_deg[d], w[e]);
        atomicAdd(&g_cnt[d], 1);
    }
}

// ---------------------------------------------------------------------------
// Exclusive prefix scan of g_cnt -> g_off (3 kernels).
__global__ void k_scan1() {
    __shared__ int sm[256];
    int t = threadIdx.x;
    int i = blockIdx.x * 256 + t;
    int v = (i < N_NODES) ? g_cnt[i] : 0;
    sm[t] = v;
    __syncthreads();
    #pragma unroll
    for (int ofs = 1; ofs < 256; ofs <<= 1) {
        int a = (t >= ofs) ? sm[t - ofs] : 0;
        __syncthreads();
        sm[t] += a;
        __syncthreads();
    }
    if (i < N_NODES) g_off[i] = sm[t] - v;
    if (t == 255) g_part[blockIdx.x] = sm[255];
}

__global__ void k_scan2() {   // single block of 512; SCAN_NB <= 512
    __shared__ int sm[512];
    int t = threadIdx.x;
    int v = (t < SCAN_NB) ? g_part[t] : 0;
    sm[t] = v;
    __syncthreads();
    #pragma unroll
    for (int ofs = 1; ofs < 512; ofs <<= 1) {
        int a = (t >= ofs) ? sm[t - ofs] : 0;
        __syncthreads();
        sm[t] += a;
        __syncthreads();
    }
    if (t < SCAN_NB) g_part[t] = sm[t] - v;
}

// K scan3: add block base, seed cursors, and compute dinv (fused).
__global__ void k_scan3() {
    int i = blockIdx.x * blockDim.x + threadIdx.x;
    if (i < N_NODES) {
        int o = g_off[i] + g_part[i >> 8];
        g_off[i] = o;
        g_cur[i] = o;
        g_dinv[i] = rsqrtf(g_deg[i]);
    }
}

// ---------------------------------------------------------------------------
// K4: bucket edges by dst: pair[pos] = (src, dinv[s]*w*dinv[d])
__global__ void k_bucket(const int* __restrict__ ei,
                         const float* __restrict__ w, int E) {
    int e = blockIdx.x * blockDim.x + threadIdx.x;
    if (e < E) {
        int s = ei[e];
        int d = ei[E + e];
        int pos = atomicAdd(&g_cur[d], 1);
        float c = g_dinv[s] * w[e] * g_dinv[d];
        g_pair[pos] = make_int2(s, __float_as_int(c));
    }
}

// ---------------------------------------------------------------------------
// K5: register-blocked SGEMM fused with self-loop epilogue.
// k unrolled by 4: a loaded as float4 (swz is a multiple of 4 so kk stays
// 4-aligned within each group), immediate-offset LDS, conflict-free banks.
#define BM 96
#define NTHREADS 96
#define XS_STRIDE 68

__global__ __launch_bounds__(NTHREADS)
void k_gemm_self(const float* __restrict__ x,
                 const float* __restrict__ W,
                 const float* __restrict__ bias,
                 float* __restrict__ out) {
    __shared__ float Ws[FDIM * FDIM];        // 16 KB
    __shared__ float xs[BM * XS_STRIDE];     // 25.5 KB

    int tid  = threadIdx.x;
    int row0 = blockIdx.x * BM;
    int nrows = min(BM, N_NODES - row0);

    {
        const float4* W4  = (const float4*)W;
        float4*       Ws4 = (float4*)Ws;
        for (int i = tid; i < FDIM * FDIM / 4; i += NTHREADS) Ws4[i] = W4[i];
    }
    {
        const float4* x4 = (const float4*)(x + (size_t)row0 * FDIM);
        #pragma unroll
        for (int i = 0; i < 16; i++) {
            int idx = tid + i * NTHREADS;
            int row = idx >> 4;
            int kq  = idx & 15;
            float4 v = (row < nrows) ? x4[row * 16 + kq]
                                     : make_float4(0.f, 0.f, 0.f, 0.f);
            int kq_s = kq ^ ((row >> 3) & 3);
            *(float4*)&xs[row * XS_STRIDE + kq_s * 4] = v;
        }
    }
    __syncthreads();

    int ty = tid >> 3;
    int tx = tid & 7;
    int swz = (ty & 3) << 2;    // multiple of 4

    float acc[8][8];
    #pragma unroll
    for (int i = 0; i < 8; i++)
        #pragma unroll
        for (int j = 0; j < 8; j++) acc[i][j] = 0.f;

    const float* xbase = &xs[(ty * 8) * XS_STRIDE];
    const float* wbase = &Ws[tx * 8];

    #pragma unroll
    for (int k0 = 0; k0 < FDIM; k0 += 4) {
        int kk0 = k0 ^ swz;                 // 4-aligned
        float4 a4[8];
        #pragma unroll
        for (int i = 0; i < 8; i++)
            a4[i] = *(const float4*)&xbase[i * XS_STRIDE + kk0];

        #pragma unroll
        for (int kk = 0; kk < 4; kk++) {
            int k = k0 + kk;
            float4 b0 = *(const float4*)&wbase[k * FDIM];
            float4 b1 = *(const float4*)&wbase[k * FDIM + 4];
            float b[8] = {b0.x, b0.y, b0.z, b0.w, b1.x, b1.y, b1.z, b1.w};
            #pragma unroll
            for (int i = 0; i < 8; i++) {
                float av = (kk == 0) ? a4[i].x : (kk == 1) ? a4[i].y
                         : (kk == 2) ? a4[i].z : a4[i].w;
                #pragma unroll
                for (int j = 0; j < 8; j++)
                    acc[i][j] += av * b[j];
            }
        }
    }

    float4 bb0 = *(const float4*)&bias[tx * 8];
    float4 bb1 = *(const float4*)&bias[tx * 8 + 4];
    float bv[8] = {bb0.x, bb0.y, bb0.z, bb0.w, bb1.x, bb1.y, bb1.z, bb1.w};

    #pragma unroll
    for (int i = 0; i < 8; i++) {
        int row = row0 + ty * 8 + i;
        if (row >= N_NODES) break;
        float di = g_dinv[row];
        float sc = 2.0f * di * di;
        size_t base = (size_t)row * FDIM + tx * 8;
        float4 h0 = make_float4(acc[i][0], acc[i][1], acc[i][2], acc[i][3]);
        float4 h1 = make_float4(acc[i][4], acc[i][5], acc[i][6], acc[i][7]);
        *(float4*)&g_h[base]     = h0;
        *(float4*)&g_h[base + 4] = h1;
        float4 o0 = make_float4(h0.x * sc + bv[0], h0.y * sc + bv[1],
                                h0.z * sc + bv[2], h0.w * sc + bv[3]);
        float4 o1 = make_float4(h1.x * sc + bv[4], h1.y * sc + bv[5],
                                h1.z * sc + bv[6], h1.w * sc + bv[7]);
        *(float4*)&out[base]     = o0;
        *(float4*)&out[base + 4] = o1;
    }
}

// ---------------------------------------------------------------------------
// K6: gather-accumulate, unrolled x4 for MLP. 16 lanes per dst node.
__global__ void k_gather(float* __restrict__ out) {
    int t = blockIdx.x * blockDim.x + threadIdx.x;
    int node = t >> 4;
    int l    = t & 15;
    if (node >= N_NODES) return;

    int start = g_off[node];
    int n     = g_cnt[node];
    const int2* pr = &g_pair[start];

    float4 acc = make_float4(0.f, 0.f, 0.f, 0.f);

    int j = 0;
    for (; j + 4 <= n; j += 4) {
        int2 p0 = pr[j];
        int2 p1 = pr[j + 1];
        int2 p2 = pr[j + 2];
        int2 p3 = pr[j + 3];
        float4 v0 = ((const float4*)(g_h + (size_t)p0.x * FDIM))[l];
        float4 v1 = ((const float4*)(g_h + (size_t)p1.x * FDIM))[l];
        float4 v2 = ((const float4*)(g_h + (size_t)p2.x * FDIM))[l];
        float4 v3 = ((const float4*)(g_h + (size_t)p3.x * FDIM))[l];
        float c0 = __int_as_float(p0.y);
        float c1 = __int_as_float(p1.y);
        float c2 = __int_as_float(p2.y);
        float c3 = __int_as_float(p3.y);
        acc.x += c0 * v0.x; acc.y += c0 * v0.y; acc.z += c0 * v0.z; acc.w += c0 * v0.w;
        acc.x += c1 * v1.x; acc.y += c1 * v1.y; acc.z += c1 * v1.z; acc.w += c1 * v1.w;
        acc.x += c2 * v2.x; acc.y += c2 * v2.y; acc.z += c2 * v2.z; acc.w += c2 * v2.w;
        acc.x += c3 * v3.x; acc.y += c3 * v3.y; acc.z += c3 * v3.z; acc.w += c3 * v3.w;
    }
    for (; j < n; j++) {
        int2 p = pr[j];
        float4 v = ((const float4*)(g_h + (size_t)p.x * FDIM))[l];
        float c = __int_as_float(p.y);
        acc.x += c * v.x; acc.y += c * v.y; acc.z += c * v.z; acc.w += c * v.w;
    }

    float4* op = (float4*)(out + (size_t)node * FDIM) + l;
    float4 o = *op;
    o.x += acc.x; o.y += acc.y; o.z += acc.z; o.w += acc.w;
    *op = o;
}

// ---------------------------------------------------------------------------
extern "C" void kernel_launch(void* const* d_in, const int* in_sizes, int n_in,
                              void* d_out, int out_size) {
    const float* x   = (const float*)d_in[0];       // [N, 64]
    const float* ew  = (const float*)d_in[1];       // [E]
    const float* W   = (const float*)d_in[2];       // [64, 64]
    const float* b   = (const float*)d_in[3];       // [64]
    const int*   ei  = (const int*)d_in[4];         // [2, E] int32
    // d_in[5] = batch, unused

    int E = in_sizes[1];
    float* out = (float*)d_out;

    k_init   <<<(N_NODES + 255) / 256, 256>>>();
    k_deg_acc<<<(E + 255) / 256, 256>>>(ei, ew, E);

    k_scan1<<<SCAN_NB, 256>>>();
    k_scan2<<<1, 512>>>();
    k_scan3<<<(N_NODES + 255) / 256, 256>>>();     // + dinv fused

    k_bucket<<<(E + 255) / 256, 256>>>(ei, ew, E);

    k_gemm_self<<<(N_NODES + BM - 1) / BM, NTHREADS>>>(x, W, b, out);

    long long gt = (long long)N_NODES * 16;
    k_gather<<<(unsigned)((gt + 255) / 256), 256>>>(out);
}

// round 8
// speedup vs baseline: 2.0153x; 1.1053x over previous
#include <cuda_runtime.h>
#include <cuda_fp16.h>
#include <cstdint>

#define N_NODES 100000
#define FDIM 64                 // IN_W == OUT_W == 64
#define SELF_LOOP_W 2.0f
#define E_MAX 2000000

// ---- scratch (no cudaMalloc allowed) ----
__device__ float  g_deg [N_NODES];
__device__ float  g_dinv[N_NODES];
__device__ __half g_h   [(size_t)N_NODES * FDIM];   // fp16 h (gather traffic /2)
__device__ int    g_cnt [N_NODES];
__device__ int    g_off [N_NODES];
__device__ int    g_cur [N_NODES];
__device__ int    g_ctr;                            // global bucket cursor
__device__ int2   g_pair[E_MAX];                    // (src, coef-bits)

// ---------------------------------------------------------------------------
// K1: deg[i] = self-loop weight ; cnt[i] = 0 ; zero global cursor
__global__ void k_init() {
    int i = blockIdx.x * blockDim.x + threadIdx.x;
    if (i < N_NODES) { g_deg[i] = SELF_LOOP_W; g_cnt[i] = 0; }
    if (i == 0) g_ctr = 0;
}

// K2: deg[dst] += w[e] ; cnt[dst]++
__global__ void k_deg_acc(const int* __restrict__ ei,
                          const float* __restrict__ w, int E) {
    int e = blockIdx.x * blockDim.x + threadIdx.x;
    if (e < E) {
        int d = ei[E + e];
        atomicAdd(&g_deg[d], w[e]);
        atomicAdd(&g_cnt[d], 1);
    }
}

// ---------------------------------------------------------------------------
// K3: per-node bucket offsets in ONE kernel. Block-local exclusive scan of
// cnt, block base from a single atomicAdd (ranges disjoint; global order
// irrelevant). Also fuses dinv = rsqrt(deg) and cursor seeding.
__global__ void k_off() {
    __shared__ int sm[256];
    __shared__ int base;
    int t = threadIdx.x;
    int i = blockIdx.x * 256 + t;
    int v = (i < N_NODES) ? g_cnt[i] : 0;
    sm[t] = v;
    __syncthreads();
    #pragma unroll
    for (int ofs = 1; ofs < 256; ofs <<= 1) {
        int a = (t >= ofs) ? sm[t - ofs] : 0;
        __syncthreads();
        sm[t] += a;
        __syncthreads();
    }
    if (t == 255) base = atomicAdd(&g_ctr, sm[255]);
    __syncthreads();
    if (i < N_NODES) {
        int o = sm[t] - v + base;
        g_off[i]  = o;
        g_cur[i]  = o;
        g_dinv[i] = rsqrtf(g_deg[i]);
    }
}

// ---------------------------------------------------------------------------
// K4: bucket edges by dst: pair[pos] = (src, dinv[s]*w*dinv[d])
__global__ void k_bucket(const int* __restrict__ ei,
                         const float* __restrict__ w, int E) {
    int e = blockIdx.x * blockDim.x + threadIdx.x;
    if (e < E) {
        int s = ei[e];
        int d = ei[E + e];
        int pos = atomicAdd(&g_cur[d], 1);
        float c = g_dinv[s] * w[e] * g_dinv[d];
        g_pair[pos] = make_int2(s, __float_as_int(c));
    }
}

// ---------------------------------------------------------------------------
// K5: register-blocked SGEMM fused with self-loop epilogue.
// out (fp32) = h*2*dinv^2 + bias ; g_h stored fp16.
#define BM 96
#define NTHREADS 96
#define XS_STRIDE 68

__global__ __launch_bounds__(NTHREADS)
void k_gemm_self(const float* __restrict__ x,
                 const float* __restrict__ W,
                 const float* __restrict__ bias,
                 float* __restrict__ out) {
    __shared__ float Ws[FDIM * FDIM];        // 16 KB
    __shared__ float xs[BM * XS_STRIDE];     // 25.5 KB

    int tid  = threadIdx.x;
    int row0 = blockIdx.x * BM;
    int nrows = min(BM, N_NODES - row0);

    {
        const float4* W4  = (const float4*)W;
        float4*       Ws4 = (float4*)Ws;
        for (int i = tid; i < FDIM * FDIM / 4; i += NTHREADS) Ws4[i] = W4[i];
    }
    {
        const float4* x4 = (const float4*)(x + (size_t)row0 * FDIM);
        #pragma unroll
        for (int i = 0; i < 16; i++) {
            int idx = tid + i * NTHREADS;
            int row = idx >> 4;
            int kq  = idx & 15;
            float4 v = (row < nrows) ? x4[row * 16 + kq]
                                     : make_float4(0.f, 0.f, 0.f, 0.f);
            int kq_s = kq ^ ((row >> 3) & 3);
            *(float4*)&xs[row * XS_STRIDE + kq_s * 4] = v;
        }
    }
    __syncthreads();

    int ty = tid >> 3;
    int tx = tid & 7;
    int swz = (ty & 3) << 2;    // multiple of 4

    float acc[8][8];
    #pragma unroll
    for (int i = 0; i < 8; i++)
        #pragma unroll
        for (int j = 0; j < 8; j++) acc[i][j] = 0.f;

    const float* xbase = &xs[(ty * 8) * XS_STRIDE];
    const float* wbase = &Ws[tx * 8];

    #pragma unroll
    for (int k0 = 0; k0 < FDIM; k0 += 4) {
        int kk0 = k0 ^ swz;                 // 4-aligned
        float4 a4[8];
        #pragma unroll
        for (int i = 0; i < 8; i++)
            a4[i] = *(const float4*)&xbase[i * XS_STRIDE + kk0];

        #pragma unroll
        for (int kk = 0; kk < 4; kk++) {
            int k = k0 + kk;
            float4 b0 = *(const float4*)&wbase[k * FDIM];
            float4 b1 = *(const float4*)&wbase[k * FDIM + 4];
            float b[8] = {b0.x, b0.y, b0.z, b0.w, b1.x, b1.y, b1.z, b1.w};
            #pragma unroll
            for (int i = 0; i < 8; i++) {
                float av = (kk == 0) ? a4[i].x : (kk == 1) ? a4[i].y
                         : (kk == 2) ? a4[i].z : a4[i].w;
                #pragma unroll
                for (int j = 0; j < 8; j++)
                    acc[i][j] += av * b[j];
            }
        }
    }

    float4 bb0 = *(const float4*)&bias[tx * 8];
    float4 bb1 = *(const float4*)&bias[tx * 8 + 4];
    float bv[8] = {bb0.x, bb0.y, bb0.z, bb0.w, bb1.x, bb1.y, bb1.z, bb1.w};

    #pragma unroll
    for (int i = 0; i < 8; i++) {
        int row = row0 + ty * 8 + i;
        if (row >= N_NODES) break;
        float di = g_dinv[row];
        float sc = 2.0f * di * di;
        size_t base = (size_t)row * FDIM + tx * 8;

        // fp16 h store: 8 halves = 16 B
        __half2 hh[4];
        hh[0] = __floats2half2_rn(acc[i][0], acc[i][1]);
        hh[1] = __floats2half2_rn(acc[i][2], acc[i][3]);
        hh[2] = __floats2half2_rn(acc[i][4], acc[i][5]);
        hh[3] = __floats2half2_rn(acc[i][6], acc[i][7]);
        *(uint4*)&g_h[base] = *(uint4*)hh;

        float4 o0 = make_float4(acc[i][0] * sc + bv[0], acc[i][1] * sc + bv[1],
                                acc[i][2] * sc + bv[2], acc[i][3] * sc + bv[3]);
        float4 o1 = make_float4(acc[i][4] * sc + bv[4], acc[i][5] * sc + bv[5],
                                acc[i][6] * sc + bv[6], acc[i][7] * sc + bv[7]);
        *(float4*)&out[base]     = o0;
        *(float4*)&out[base + 4] = o1;
    }
}

// ---------------------------------------------------------------------------
// K6: gather-accumulate over fp16 h, unrolled x4. 16 lanes per node,
// 8 B (4 halves) per lane -> 128 B coalesced row reads.
__device__ __forceinline__ void acc_half4(float4& acc, uint2 u, float c) {
    float2 f0 = __half22float2(*(__half2*)&u.x);
    float2 f1 = __half22float2(*(__half2*)&u.y);
    acc.x += c * f0.x; acc.y += c * f0.y;
    acc.z += c * f1.x; acc.w += c * f1.y;
}

__global__ void k_gather(float* __restrict__ out) {
    int t = blockIdx.x * blockDim.x + threadIdx.x;
    int node = t >> 4;
    int l    = t & 15;
    if (node >= N_NODES) return;

    int start = g_off[node];
    int n     = g_cnt[node];
    const int2* pr = &g_pair[start];

    float4 acc = make_float4(0.f, 0.f, 0.f, 0.f);

    int j = 0;
    for (; j + 4 <= n; j += 4) {
        int2 p0 = pr[j];
        int2 p1 = pr[j + 1];
        int2 p2 = pr[j + 2];
        int2 p3 = pr[j + 3];
        uint2 v0 = ((const uint2*)(g_h + (size_t)p0.x * FDIM))[l];
        uint2 v1 = ((const uint2*)(g_h + (size_t)p1.x * FDIM))[l];
        uint2 v2 = ((const uint2*)(g_h + (size_t)p2.x * FDIM))[l];
        uint2 v3 = ((const uint2*)(g_h + (size_t)p3.x * FDIM))[l];
        acc_half4(acc, v0, __int_as_float(p0.y));
        acc_half4(acc, v1, __int_as_float(p1.y));
        acc_half4(acc, v2, __int_as_float(p2.y));
        acc_half4(acc, v3, __int_as_float(p3.y));
    }
    for (; j < n; j++) {
        int2 p = pr[j];
        uint2 v = ((const uint2*)(g_h + (size_t)p.x * FDIM))[l];
        acc_half4(acc, v, __int_as_float(p.y));
    }

    float4* op = (float4*)(out + (size_t)node * FDIM) + l;
    float4 o = *op;
    o.x += acc.x; o.y += acc.y; o.z += acc.z; o.w += acc.w;
    *op = o;
}

// ---------------------------------------------------------------------------
extern "C" void kernel_launch(void* const* d_in, const int* in_sizes, int n_in,
                              void* d_out, int out_size) {
    const float* x   = (const float*)d_in[0];       // [N, 64]
    const float* ew  = (const float*)d_in[1];       // [E]
    const float* W   = (const float*)d_in[2];       // [64, 64]
    const float* b   = (const float*)d_in[3];       // [64]
    const int*   ei  = (const int*)d_in[4];         // [2, E] int32
    // d_in[5] = batch, unused

    int E = in_sizes[1];
    float* out = (float*)d_out;

    k_init   <<<(N_NODES + 255) / 256, 256>>>();
    k_deg_acc<<<(E + 255) / 256, 256>>>(ei, ew, E);
    k_off    <<<(N_NODES + 255) / 256, 256>>>();
    k_bucket <<<(E + 255) / 256, 256>>>(ei, ew, E);
    k_gemm_self<<<(N_NODES + BM - 1) / BM, NTHREADS>>>(x, W, b, out);

    long long gt = (long long)N_NODES * 16;
    k_gather<<<(unsigned)((gt + 255) / 256), 256>>>(out);
}

// round 9
// speedup vs baseline: 2.1339x; 1.0588x over previous
#include <cuda_runtime.h>
#include <cuda_fp16.h>
#include <cstdint>

#define N_NODES 100000
#define FDIM 64                 // IN_W == OUT_W == 64
#define E_MAX 2000000

// ---- scratch (no cudaMalloc allowed) ----
// g_pk[i]: bits[40:64) = edge count, bits[0:40) = fixed-point sum(w)*2^32
__device__ unsigned long long g_pk[N_NODES];
__device__ float  g_dinv[N_NODES];
__device__ __half g_h   [(size_t)N_NODES * FDIM];   // fp16 h (gather traffic /2)
__device__ int    g_cnt [N_NODES];
__device__ int    g_off [N_NODES];
__device__ int    g_cur [N_NODES];
__device__ int    g_ctr;                            // global bucket cursor
__device__ int2   g_pair[E_MAX];                    // (src, w-bits)

#define PK_SELF (2ULL << 32)                        // deg = 2.0 fixed-point
#define PK_CNT1 (1ULL << 40)
#define PK_DEGMASK ((1ULL << 40) - 1)

// ---------------------------------------------------------------------------
// K1: pk[i] = (cnt=0, deg=2.0) ; zero global cursor
__global__ void k_init() {
    int i = blockIdx.x * blockDim.x + threadIdx.x;
    if (i < N_NODES) g_pk[i] = PK_SELF;
    if (i == 0) g_ctr = 0;
}

// K2: single fused 64-bit atomic: cnt++ and deg += w (fixed point)
__global__ void k_deg_acc(const int* __restrict__ ei,
                          const float* __restrict__ w, int E) {
    int e = blockIdx.x * blockDim.x + threadIdx.x;
    if (e < E) {
        int d = ei[E + e];
        // w in [0,1): w * 2^32 is an exact fp32 exponent shift
        unsigned long long add =
            PK_CNT1 + (unsigned long long)(w[e] * 4294967296.0f);
        atomicAdd(&g_pk[d], add);
    }
}

// ---------------------------------------------------------------------------
// K3: unpack (cnt, deg); block-local exclusive scan of cnt; block base from
// one atomicAdd (ranges disjoint, global order irrelevant); fuse dinv.
__global__ void k_off() {
    __shared__ int sm[256];
    __shared__ int base;
    int t = threadIdx.x;
    int i = blockIdx.x * 256 + t;

    int v = 0; float dinv = 0.f;
    if (i < N_NODES) {
        unsigned long long pk = g_pk[i];
        v = (int)(pk >> 40);
        float deg = (float)((double)(pk & PK_DEGMASK) * (1.0 / 4294967296.0));
        dinv = rsqrtf(deg);
    }
    sm[t] = v;
    __syncthreads();
    #pragma unroll
    for (int ofs = 1; ofs < 256; ofs <<= 1) {
        int a = (t >= ofs) ? sm[t - ofs] : 0;
        __syncthreads();
        sm[t] += a;
        __syncthreads();
    }
    if (t == 255) base = atomicAdd(&g_ctr, sm[255]);
    __syncthreads();
    if (i < N_NODES) {
        int o = sm[t] - v + base;
        g_off[i]  = o;
        g_cur[i]  = o;
        g_cnt[i]  = v;
        g_dinv[i] = dinv;
    }
}

// ---------------------------------------------------------------------------
// K4: bucket edges by dst: pair[pos] = (src, w-bits). NO dinv loads here —
// coef is computed in the gather where dinv access is cheap/broadcast.
__global__ void k_bucket(const int* __restrict__ ei,
                         const float* __restrict__ w, int E) {
    int e = blockIdx.x * blockDim.x + threadIdx.x;
    if (e < E) {
        int s = ei[e];
        int d = ei[E + e];
        int pos = atomicAdd(&g_cur[d], 1);
        g_pair[pos] = make_int2(s, __float_as_int(w[e]));
    }
}

// ---------------------------------------------------------------------------
// K5: register-blocked SGEMM fused with self-loop epilogue.
// out (fp32) = h*2*dinv^2 + bias ; g_h stored fp16.
#define BM 96
#define NTHREADS 96
#define XS_STRIDE 68

__global__ __launch_bounds__(NTHREADS)
void k_gemm_self(const float* __restrict__ x,
                 const float* __restrict__ W,
                 const float* __restrict__ bias,
                 float* __restrict__ out) {
    __shared__ float Ws[FDIM * FDIM];        // 16 KB
    __shared__ float xs[BM * XS_STRIDE];     // 25.5 KB

    int tid  = threadIdx.x;
    int row0 = blockIdx.x * BM;
    int nrows = min(BM, N_NODES - row0);

    {
        const float4* W4  = (const float4*)W;
        float4*       Ws4 = (float4*)Ws;
        for (int i = tid; i < FDIM * FDIM / 4; i += NTHREADS) Ws4[i] = W4[i];
    }
    {
        const float4* x4 = (const float4*)(x + (size_t)row0 * FDIM);
        #pragma unroll
        for (int i = 0; i < 16; i++) {
            int idx = tid + i * NTHREADS;
            int row = idx >> 4;
            int kq  = idx & 15;
            float4 v = (row < nrows) ? x4[row * 16 + kq]
                                     : make_float4(0.f, 0.f, 0.f, 0.f);
            int kq_s = kq ^ ((row >> 3) & 3);
            *(float4*)&xs[row * XS_STRIDE + kq_s * 4] = v;
        }
    }
    __syncthreads();

    int ty = tid >> 3;
    int tx = tid & 7;
    int swz = (ty & 3) << 2;    // multiple of 4

    float acc[8][8];
    #pragma unroll
    for (int i = 0; i < 8; i++)
        #pragma unroll
        for (int j = 0; j < 8; j++) acc[i][j] = 0.f;

    const float* xbase = &xs[(ty * 8) * XS_STRIDE];
    const float* wbase = &Ws[tx * 8];

    #pragma unroll
    for (int k0 = 0; k0 < FDIM; k0 += 4) {
        int kk0 = k0 ^ swz;                 // 4-aligned
        float4 a4[8];
        #pragma unroll
        for (int i = 0; i < 8; i++)
            a4[i] = *(const float4*)&xbase[i * XS_STRIDE + kk0];

        #pragma unroll
        for (int kk = 0; kk < 4; kk++) {
            int k = k0 + kk;
            float4 b0 = *(const float4*)&wbase[k * FDIM];
            float4 b1 = *(const float4*)&wbase[k * FDIM + 4];
            float b[8] = {b0.x, b0.y, b0.z, b0.w, b1.x, b1.y, b1.z, b1.w};
            #pragma unroll
            for (int i = 0; i < 8; i++) {
                float av = (kk == 0) ? a4[i].x : (kk == 1) ? a4[i].y
                         : (kk == 2) ? a4[i].z : a4[i].w;
                #pragma unroll
                for (int j = 0; j < 8; j++)
                    acc[i][j] += av * b[j];
            }
        }
    }

    float4 bb0 = *(const float4*)&bias[tx * 8];
    float4 bb1 = *(const float4*)&bias[tx * 8 + 4];
    float bv[8] = {bb0.x, bb0.y, bb0.z, bb0.w, bb1.x, bb1.y, bb1.z, bb1.w};

    #pragma unroll
    for (int i = 0; i < 8; i++) {
        int row = row0 + ty * 8 + i;
        if (row >= N_NODES) break;
        float di = g_dinv[row];
        float sc = 2.0f * di * di;
        size_t base = (size_t)row * FDIM + tx * 8;

        __half2 hh[4];
        hh[0] = __floats2half2_rn(acc[i][0], acc[i][1]);
        hh[1] = __floats2half2_rn(acc[i][2], acc[i][3]);
        hh[2] = __floats2half2_rn(acc[i][4], acc[i][5]);
        hh[3] = __floats2half2_rn(acc[i][6], acc[i][7]);
        *(uint4*)&g_h[base] = *(uint4*)hh;

        float4 o0 = make_float4(acc[i][0] * sc + bv[0], acc[i][1] * sc + bv[1],
                                acc[i][2] * sc + bv[2], acc[i][3] * sc + bv[3]);
        float4 o1 = make_float4(acc[i][4] * sc + bv[4], acc[i][5] * sc + bv[5],
                                acc[i][6] * sc + bv[6], acc[i][7] * sc + bv[7]);
        *(float4*)&out[base]     = o0;
        *(float4*)&out[base + 4] = o1;
    }
}

// ---------------------------------------------------------------------------
// K6: gather-accumulate over fp16 h, unrolled x4. 16 lanes per node.
// coef = dinv[s]*w accumulated per edge; dinv[d] factored out (linear).
__device__ __forceinline__ void acc_half4(float4& acc, uint2 u, float c) {
    float2 f0 = __half22float2(*(__half2*)&u.x);
    float2 f1 = __half22float2(*(__half2*)&u.y);
    acc.x += c * f0.x; acc.y += c * f0.y;
    acc.z += c * f1.x; acc.w += c * f1.y;
}

__global__ void k_gather(float* __restrict__ out) {
    int t = blockIdx.x * blockDim.x + threadIdx.x;
    int node = t >> 4;
    int l    = t & 15;
    if (node >= N_NODES) return;

    int start = g_off[node];
    int n     = g_cnt[node];
    const int2* pr = &g_pair[start];

    float4 acc = make_float4(0.f, 0.f, 0.f, 0.f);

    int j = 0;
    for (; j + 4 <= n; j += 4) {
        int2 p0 = pr[j];
        int2 p1 = pr[j + 1];
        int2 p2 = pr[j + 2];
        int2 p3 = pr[j + 3];
        uint2 v0 = ((const uint2*)(g_h + (size_t)p0.x * FDIM))[l];
        uint2 v1 = ((const uint2*)(g_h + (size_t)p1.x * FDIM))[l];
        uint2 v2 = ((const uint2*)(g_h + (size_t)p2.x * FDIM))[l];
        uint2 v3 = ((const uint2*)(g_h + (size_t)p3.x * FDIM))[l];
        float c0 = g_dinv[p0.x] * __int_as_float(p0.y);
        float c1 = g_dinv[p1.x] * __int_as_float(p1.y);
        float c2 = g_dinv[p2.x] * __int_as_float(p2.y);
        float c3 = g_dinv[p3.x] * __int_as_float(p3.y);
        acc_half4(acc, v0, c0);
        acc_half4(acc, v1, c1);
        acc_half4(acc, v2, c2);
        acc_half4(acc, v3, c3);
    }
    for (; j < n; j++) {
        int2 p = pr[j];
        uint2 v = ((const uint2*)(g_h + (size_t)p.x * FDIM))[l];
        acc_half4(acc, v, g_dinv[p.x] * __int_as_float(p.y));
    }

    float dd = g_dinv[node];
    float4* op = (float4*)(out + (size_t)node * FDIM) + l;
    float4 o = *op;
    o.x += dd * acc.x; o.y += dd * acc.y;
    o.z += dd * acc.z; o.w += dd * acc.w;
    *op = o;
}

// ---------------------------------------------------------------------------
extern "C" void kernel_launch(void* const* d_in, const int* in_sizes, int n_in,
                              void* d_out, int out_size) {
    const float* x   = (const float*)d_in[0];       // [N, 64]
    const float* ew  = (const float*)d_in[1];       // [E]
    const float* W   = (const float*)d_in[2];       // [64, 64]
    const float* b   = (const float*)d_in[3];       // [64]
    const int*   ei  = (const int*)d_in[4];         // [2, E] int32
    // d_in[5] = batch, unused

    int E = in_sizes[1];
    float* out = (float*)d_out;

    k_init   <<<(N_NODES + 255) / 256, 256>>>();
    k_deg_acc<<<(E + 255) / 256, 256>>>(ei, ew, E);
    k_off    <<<(N_NODES + 255) / 256, 256>>>();
    k_bucket <<<(E + 255) / 256, 256>>>(ei, ew, E);
    k_gemm_self<<<(N_NODES + BM - 1) / BM, NTHREADS>>>(x, W, b, out);

    long long gt = (long long)N_NODES * 16;
    k_gather<<<(unsigned)((gt + 255) / 256), 256>>>(out);
}

// round 10
// speedup vs baseline: 2.5086x; 1.1756x over previous
#include <cuda_runtime.h>
#include <cuda_fp16.h>
#include <cstdint>

#define N_NODES 100000
#define FDIM 64                 // IN_W == OUT_W == 64
#define E_MAX 2000000

// ---- scratch (no cudaMalloc allowed) ----
// g_pk[i]: bits[40:64) = edge count, bits[0:40) = fixed-point sum(w)*2^32
__device__ unsigned long long g_pk[N_NODES];
__device__ float  g_dinv[N_NODES];
__device__ __half g_h   [(size_t)N_NODES * FDIM];   // fp16 h
__device__ int    g_cnt [N_NODES];
__device__ int    g_off [N_NODES];
__device__ int    g_cur [N_NODES];
__device__ int    g_ctr;                            // global bucket cursor
__device__ int2   g_pair[E_MAX];                    // (src, w-bits)

#define PK_SELF (2ULL << 32)                        // deg = 2.0 fixed-point
#define PK_CNT1 (1ULL << 40)
#define PK_DEGMASK ((1ULL << 40) - 1)

// ---------------------------------------------------------------------------
// K1: pk[i] = (cnt=0, deg=2.0) ; zero global cursor
__global__ void k_init() {
    int i = blockIdx.x * blockDim.x + threadIdx.x;
    if (i < N_NODES) g_pk[i] = PK_SELF;
    if (i == 0) g_ctr = 0;
}

// K2: single fused 64-bit atomic: cnt++ and deg += w (fixed point)
__global__ void k_deg_acc(const int* __restrict__ ei,
                          const float* __restrict__ w, int E) {
    int e = blockIdx.x * blockDim.x + threadIdx.x;
    if (e < E) {
        int d = ei[E + e];
        unsigned long long add =
            PK_CNT1 + (unsigned long long)(w[e] * 4294967296.0f);
        atomicAdd(&g_pk[d], add);
    }
}

// ---------------------------------------------------------------------------
// K3: unpack (cnt, deg); block-local exclusive scan; block base from one
// atomicAdd (ranges disjoint, global order irrelevant); fuse dinv.
__global__ void k_off() {
    __shared__ int sm[256];
    __shared__ int base;
    int t = threadIdx.x;
    int i = blockIdx.x * 256 + t;

    int v = 0; float dinv = 0.f;
    if (i < N_NODES) {
        unsigned long long pk = g_pk[i];
        v = (int)(pk >> 40);
        float deg = (float)((double)(pk & PK_DEGMASK) * (1.0 / 4294967296.0));
        dinv = rsqrtf(deg);
    }
    sm[t] = v;
    __syncthreads();
    #pragma unroll
    for (int ofs = 1; ofs < 256; ofs <<= 1) {
        int a = (t >= ofs) ? sm[t - ofs] : 0;
        __syncthreads();
        sm[t] += a;
        __syncthreads();
    }
    if (t == 255) base = atomicAdd(&g_ctr, sm[255]);
    __syncthreads();
    if (i < N_NODES) {
        int o = sm[t] - v + base;
        g_off[i]  = o;
        g_cur[i]  = o;
        g_cnt[i]  = v;
        g_dinv[i] = dinv;
    }
}

// ---------------------------------------------------------------------------
// K4: bucket edges by dst: pair[pos] = (src, w-bits).
__global__ void k_bucket(const int* __restrict__ ei,
                         const float* __restrict__ w, int E) {
    int e = blockIdx.x * blockDim.x + threadIdx.x;
    if (e < E) {
        int s = ei[e];
        int d = ei[E + e];
        int pos = atomicAdd(&g_cur[d], 1);
        g_pair[pos] = make_int2(s, __float_as_int(w[e]));
    }
}

// ---------------------------------------------------------------------------
// K5: register-blocked SGEMM, h only (fp16). NO epilogue -> no dependency on
// the edge chain; runs on a side stream concurrently with it.
#define BM 96
#define NTHREADS 96
#define XS_STRIDE 68

__global__ __launch_bounds__(NTHREADS)
void k_gemm(const float* __restrict__ x, const float* __restrict__ W) {
    __shared__ float Ws[FDIM * FDIM];        // 16 KB
    __shared__ float xs[BM * XS_STRIDE];     // 25.5 KB

    int tid  = threadIdx.x;
    int row0 = blockIdx.x * BM;
    int nrows = min(BM, N_NODES - row0);

    {
        const float4* W4  = (const float4*)W;
        float4*       Ws4 = (float4*)Ws;
        for (int i = tid; i < FDIM * FDIM / 4; i += NTHREADS) Ws4[i] = W4[i];
    }
    {
        const float4* x4 = (const float4*)(x + (size_t)row0 * FDIM);
        #pragma unroll
        for (int i = 0; i < 16; i++) {
            int idx = tid + i * NTHREADS;
            int row = idx >> 4;
            int kq  = idx & 15;
            float4 v = (row < nrows) ? x4[row * 16 + kq]
                                     : make_float4(0.f, 0.f, 0.f, 0.f);
            int kq_s = kq ^ ((row >> 3) & 3);
            *(float4*)&xs[row * XS_STRIDE + kq_s * 4] = v;
        }
    }
    __syncthreads();

    int ty = tid >> 3;
    int tx = tid & 7;
    int swz = (ty & 3) << 2;

    float acc[8][8];
    #pragma unroll
    for (int i = 0; i < 8; i++)
        #pragma unroll
        for (int j = 0; j < 8; j++) acc[i][j] = 0.f;

    const float* xbase = &xs[(ty * 8) * XS_STRIDE];
    const float* wbase = &Ws[tx * 8];

    #pragma unroll
    for (int k0 = 0; k0 < FDIM; k0 += 4) {
        int kk0 = k0 ^ swz;
        float4 a4[8];
        #pragma unroll
        for (int i = 0; i < 8; i++)
            a4[i] = *(const float4*)&xbase[i * XS_STRIDE + kk0];

        #pragma unroll
        for (int kk = 0; kk < 4; kk++) {
            int k = k0 + kk;
            float4 b0 = *(const float4*)&wbase[k * FDIM];
            float4 b1 = *(const float4*)&wbase[k * FDIM + 4];
            float b[8] = {b0.x, b0.y, b0.z, b0.w, b1.x, b1.y, b1.z, b1.w};
            #pragma unroll
            for (int i = 0; i < 8; i++) {
                float av = (kk == 0) ? a4[i].x : (kk == 1) ? a4[i].y
                         : (kk == 2) ? a4[i].z : a4[i].w;
                #pragma unroll
                for (int j = 0; j < 8; j++)
                    acc[i][j] += av * b[j];
            }
        }
    }

    #pragma unroll
    for (int i = 0; i < 8; i++) {
        int row = row0 + ty * 8 + i;
        if (row >= N_NODES) break;
        size_t base = (size_t)row * FDIM + tx * 8;
        __half2 hh[4];
        hh[0] = __floats2half2_rn(acc[i][0], acc[i][1]);
        hh[1] = __floats2half2_rn(acc[i][2], acc[i][3]);
        hh[2] = __floats2half2_rn(acc[i][4], acc[i][5]);
        hh[3] = __floats2half2_rn(acc[i][6], acc[i][7]);
        *(uint4*)&g_h[base] = *(uint4*)hh;
    }
}

// ---------------------------------------------------------------------------
// K6: gather. Sole writer of out:
//   out[d] = dinv_d * ( sum_e dinv_s*w*h[s]  +  2*dinv_d*h[d] ) + bias
__device__ __forceinline__ void acc_half4(float4& acc, uint2 u, float c) {
    float2 f0 = __half22float2(*(__half2*)&u.x);
    float2 f1 = __half22float2(*(__half2*)&u.y);
    acc.x += c * f0.x; acc.y += c * f0.y;
    acc.z += c * f1.x; acc.w += c * f1.y;
}

__global__ void k_gather(const float* __restrict__ bias,
                         float* __restrict__ out) {
    int t = blockIdx.x * blockDim.x + threadIdx.x;
    int node = t >> 4;
    int l    = t & 15;
    if (node >= N_NODES) return;

    int start = g_off[node];
    int n     = g_cnt[node];
    const int2* pr = &g_pair[start];

    float dd = g_dinv[node];
    float4 acc = make_float4(0.f, 0.f, 0.f, 0.f);

    // self loop: + 2*dd * h[node]
    {
        uint2 hv = ((const uint2*)(g_h + (size_t)node * FDIM))[l];
        acc_half4(acc, hv, 2.0f * dd);
    }

    int j = 0;
    for (; j + 4 <= n; j += 4) {
        int2 p0 = pr[j];
        int2 p1 = pr[j + 1];
        int2 p2 = pr[j + 2];
        int2 p3 = pr[j + 3];
        uint2 v0 = ((const uint2*)(g_h + (size_t)p0.x * FDIM))[l];
        uint2 v1 = ((const uint2*)(g_h + (size_t)p1.x * FDIM))[l];
        uint2 v2 = ((const uint2*)(g_h + (size_t)p2.x * FDIM))[l];
        uint2 v3 = ((const uint2*)(g_h + (size_t)p3.x * FDIM))[l];
        float c0 = g_dinv[p0.x] * __int_as_float(p0.y);
        float c1 = g_dinv[p1.x] * __int_as_float(p1.y);
        float c2 = g_dinv[p2.x] * __int_as_float(p2.y);
        float c3 = g_dinv[p3.x] * __int_as_float(p3.y);
        acc_half4(acc, v0, c0);
        acc_half4(acc, v1, c1);
        acc_half4(acc, v2, c2);
        acc_half4(acc, v3, c3);
    }
    for (; j < n; j++) {
        int2 p = pr[j];
        uint2 v = ((const uint2*)(g_h + (size_t)p.x * FDIM))[l];
        acc_half4(acc, v, g_dinv[p.x] * __int_as_float(p.y));
    }

    float4 bv = ((const float4*)bias)[l];
    float4 o = make_float4(dd * acc.x + bv.x, dd * acc.y + bv.y,
                           dd * acc.z + bv.z, dd * acc.w + bv.w);
    ((float4*)(out + (size_t)node * FDIM))[l] = o;
}

// ---------------------------------------------------------------------------
extern "C" void kernel_launch(void* const* d_in, const int* in_sizes, int n_in,
                              void* d_out, int out_size) {
    const float* x   = (const float*)d_in[0];       // [N, 64]
    const float* ew  = (const float*)d_in[1];       // [E]
    const float* W   = (const float*)d_in[2];       // [64, 64]
    const float* b   = (const float*)d_in[3];       // [64]
    const int*   ei  = (const int*)d_in[4];         // [2, E] int32
    // d_in[5] = batch, unused

    int E = in_sizes[1];
    float* out = (float*)d_out;

    // Side stream + events, created once on the first (uncaptured) call.
    // No device memory is allocated; per-call work is identical.
    static cudaStream_t s2 = nullptr;
    static cudaEvent_t  ev_fork = nullptr, ev_join = nullptr;
    if (s2 == nullptr) {
        cudaStreamCreateWithFlags(&s2, cudaStreamNonBlocking);
        cudaEventCreateWithFlags(&ev_fork, cudaEventDisableTiming);
        cudaEventCreateWithFlags(&ev_join, cudaEventDisableTiming);
    }

    // Fork: GEMM (FFMA-bound) on s2, edge chain (L2-bound) on main stream.
    cudaEventRecord(ev_fork, 0);
    cudaStreamWaitEvent(s2, ev_fork, 0);
    k_gemm<<<(N_NODES + BM - 1) / BM, NTHREADS, 0, s2>>>(x, W);
    cudaEventRecord(ev_join, s2);

    k_init   <<<(N_NODES + 255) / 256, 256>>>();
    k_deg_acc<<<(E + 255) / 256, 256>>>(ei, ew, E);
    k_off    <<<(N_NODES + 255) / 256, 256>>>();
    k_bucket <<<(E + 255) / 256, 256>>>(ei, ew, E);

    // Join, then gather (sole writer of out).
    cudaStreamWaitEvent(0, ev_join, 0);
    long long gt = (long long)N_NODES * 16;
    k_gather<<<(unsigned)((gt + 255) / 256), 256>>>(b, out);
}